// round 1
// baseline (speedup 1.0000x reference)
#include <cuda_runtime.h>
#include <math.h>

#define C 256
#define B 16
#define RPW 64            // rows per warp in pass 1
#define WPB 8             // warps per block

// Scratch accumulators (device globals: no allocation allowed in kernel_launch)
__device__ float g_S1[B * C];   // sum_b  sig(l)*e^g * x
__device__ float g_S2[B * C];   // sum_b  sig(l)*e^g * x^2
__device__ float g_Z[B];        // sum_b  e^g
__device__ float g_W[B];        // sum_b  sig(l)*e^g
__device__ float g_mean[C];
__device__ float g_rstd[C];

// ---------------------------------------------------------------------------
// zero accumulators (graph replays reuse the globals)
// ---------------------------------------------------------------------------
__global__ void zero_acc_kernel() {
    int i = blockIdx.x * blockDim.x + threadIdx.x;
    if (i < B * C) { g_S1[i] = 0.f; g_S2[i] = 0.f; }
    if (i < B)     { g_Z[i]  = 0.f; g_W[i]  = 0.f; }
}

// ---------------------------------------------------------------------------
// pass 1: one warp per 64-row chunk; each lane owns 8 channels
// (c = lane*4..lane*4+3 and 128+lane*4..128+lane*4+3 via two float4 loads)
// ---------------------------------------------------------------------------
__device__ __forceinline__ void flush_acc(int segv, int lane,
                                          float* s1, float* s2,
                                          float zacc, float wacc) {
    int c0 = lane * 4;
    int c1 = 128 + lane * 4;
#pragma unroll
    for (int k = 0; k < 4; k++) {
        atomicAdd(&g_S1[segv * C + c0 + k], s1[k]);
        atomicAdd(&g_S1[segv * C + c1 + k], s1[4 + k]);
        atomicAdd(&g_S2[segv * C + c0 + k], s2[k]);
        atomicAdd(&g_S2[segv * C + c1 + k], s2[4 + k]);
    }
    if (lane == 0) {
        atomicAdd(&g_Z[segv], zacc);
        atomicAdd(&g_W[segv], wacc);
    }
}

__device__ __forceinline__ void process_row(
    float4 x0, float4 x1, int s, int lane,
    float4 wl0, float4 wl1, float4 wg0, float4 wg1,
    float blv, float bgv,
    int& cur, float* s1, float* s2, float& zacc, float& wacc)
{
    if (s != cur) {  // rare: segment_ids sorted, <=15 boundaries globally
        flush_acc(cur, lane, s1, s2, zacc, wacc);
#pragma unroll
        for (int k = 0; k < 8; k++) { s1[k] = 0.f; s2[k] = 0.f; }
        zacc = 0.f; wacc = 0.f;
        cur = s;
    }
    float dl = x0.x*wl0.x + x0.y*wl0.y + x0.z*wl0.z + x0.w*wl0.w
             + x1.x*wl1.x + x1.y*wl1.y + x1.z*wl1.z + x1.w*wl1.w;
    float dg = x0.x*wg0.x + x0.y*wg0.y + x0.z*wg0.z + x0.w*wg0.w
             + x1.x*wg1.x + x1.y*wg1.y + x1.z*wg1.z + x1.w*wg1.w;
#pragma unroll
    for (int o = 16; o; o >>= 1) {
        dl += __shfl_xor_sync(0xffffffffu, dl, o);
        dg += __shfl_xor_sync(0xffffffffu, dg, o);
    }
    float l = dl + blv;
    float g = dg + bgv;
    float e   = __expf(g);                       // g ~ N(0,1): safe unshifted
    float sgm = 1.0f / (1.0f + __expf(-l));
    float wr  = sgm * e;
    zacc += e;
    wacc += wr;
    float t;
    t = wr * x0.x; s1[0] += t; s2[0] += t * x0.x;
    t = wr * x0.y; s1[1] += t; s2[1] += t * x0.y;
    t = wr * x0.z; s1[2] += t; s2[2] += t * x0.z;
    t = wr * x0.w; s1[3] += t; s2[3] += t * x0.w;
    t = wr * x1.x; s1[4] += t; s2[4] += t * x1.x;
    t = wr * x1.y; s1[5] += t; s2[5] += t * x1.y;
    t = wr * x1.z; s1[6] += t; s2[6] += t * x1.z;
    t = wr * x1.w; s1[7] += t; s2[7] += t * x1.w;
}

__global__ __launch_bounds__(WPB * 32)
void pass1_kernel(const float* __restrict__ feats,
                  const int*   __restrict__ seg,
                  const float* __restrict__ wl,
                  const float* __restrict__ bl,
                  const float* __restrict__ wg,
                  const float* __restrict__ bg,
                  int n)
{
    int warp = blockIdx.x * WPB + (threadIdx.x >> 5);
    int lane = threadIdx.x & 31;
    int r0 = warp * RPW;
    if (r0 >= n) return;
    int r1 = min(n, r0 + RPW);

    const float4* wl4 = (const float4*)wl;
    const float4* wg4 = (const float4*)wg;
    float4 wl0 = wl4[lane],      wl1 = wl4[32 + lane];
    float4 wg0 = wg4[lane],      wg1 = wg4[32 + lane];
    float  blv = bl[0],          bgv = bg[0];

    float s1[8], s2[8];
#pragma unroll
    for (int k = 0; k < 8; k++) { s1[k] = 0.f; s2[k] = 0.f; }
    float zacc = 0.f, wacc = 0.f;
    int cur = seg[r0];

    int r = r0;
    // batch 4 rows per iteration: 8 independent LDG.128 in flight per warp
    for (; r + 4 <= r1; r += 4) {
        const float4* ra = (const float4*)(feats + (size_t)(r + 0) * C);
        const float4* rb = (const float4*)(feats + (size_t)(r + 1) * C);
        const float4* rc = (const float4*)(feats + (size_t)(r + 2) * C);
        const float4* rd = (const float4*)(feats + (size_t)(r + 3) * C);
        float4 xa0 = ra[lane], xa1 = ra[32 + lane];
        float4 xb0 = rb[lane], xb1 = rb[32 + lane];
        float4 xc0 = rc[lane], xc1 = rc[32 + lane];
        float4 xd0 = rd[lane], xd1 = rd[32 + lane];
        int sa = seg[r], sb = seg[r + 1], sc = seg[r + 2], sd = seg[r + 3];
        process_row(xa0, xa1, sa, lane, wl0, wl1, wg0, wg1, blv, bgv, cur, s1, s2, zacc, wacc);
        process_row(xb0, xb1, sb, lane, wl0, wl1, wg0, wg1, blv, bgv, cur, s1, s2, zacc, wacc);
        process_row(xc0, xc1, sc, lane, wl0, wl1, wg0, wg1, blv, bgv, cur, s1, s2, zacc, wacc);
        process_row(xd0, xd1, sd, lane, wl0, wl1, wg0, wg1, blv, bgv, cur, s1, s2, zacc, wacc);
    }
    for (; r < r1; ++r) {
        const float4* rp = (const float4*)(feats + (size_t)r * C);
        float4 x0 = rp[lane], x1 = rp[32 + lane];
        int s = seg[r];
        process_row(x0, x1, s, lane, wl0, wl1, wg0, wg1, blv, bgv, cur, s1, s2, zacc, wacc);
    }
    flush_acc(cur, lane, s1, s2, zacc, wacc);
}

// ---------------------------------------------------------------------------
// finalize: fold 16 segments into mean[c], rstd[c]   (one block, 256 threads)
// ---------------------------------------------------------------------------
__global__ void finalize_kernel() {
    __shared__ float invZ[B];
    __shared__ float invU;
    int t = threadIdx.x;
    if (t < B) invZ[t] = 1.0f / g_Z[t];
    __syncthreads();
    if (t == 0) {
        float U = 0.f;
        for (int b = 0; b < B; b++) U += g_W[b] * invZ[b];
        invU = 1.0f / U;
    }
    __syncthreads();
    float m1 = 0.f, m2 = 0.f;
    for (int b = 0; b < B; b++) {
        m1 += g_S1[b * C + t] * invZ[b];
        m2 += g_S2[b * C + t] * invZ[b];
    }
    float iu = invU;
    m1 *= iu;
    m2 *= iu;
    float var = m2 - m1 * m1;     // sum(weight)==1 exactly in the math
    g_mean[t] = m1;
    g_rstd[t] = 1.0f / sqrtf(var);
}

// ---------------------------------------------------------------------------
// pass 2: out = (x - mean[c]) * rstd[c], float4 vectorized
// ---------------------------------------------------------------------------
__global__ __launch_bounds__(256)
void normalize_kernel(const float* __restrict__ feats,
                      float* __restrict__ out, int total4)
{
    int i = blockIdx.x * blockDim.x + threadIdx.x;
    if (i >= total4) return;
    const float4* f4 = (const float4*)feats;
    float4*       o4 = (float4*)out;
    const float4* m4 = (const float4*)g_mean;
    const float4* r4 = (const float4*)g_rstd;
    int cf = i & 63;                 // C/4 = 64 float4 per row
    float4 x = f4[i];
    float4 m = m4[cf];
    float4 rs = r4[cf];
    float4 y;
    y.x = (x.x - m.x) * rs.x;
    y.y = (x.y - m.y) * rs.y;
    y.z = (x.z - m.z) * rs.z;
    y.w = (x.w - m.w) * rs.w;
    o4[i] = y;
}

// ---------------------------------------------------------------------------
extern "C" void kernel_launch(void* const* d_in, const int* in_sizes, int n_in,
                              void* d_out, int out_size) {
    const float* feats = (const float*)d_in[0];
    const int*   seg   = (const int*)  d_in[1];
    const float* wl    = (const float*)d_in[2];
    const float* bl    = (const float*)d_in[3];
    const float* wg    = (const float*)d_in[4];
    const float* bg    = (const float*)d_in[5];
    float*       out   = (float*)d_out;

    int n = in_sizes[0] / C;

    zero_acc_kernel<<<(B * C + 255) / 256, 256>>>();

    int warps  = (n + RPW - 1) / RPW;
    int blocks = (warps + WPB - 1) / WPB;
    pass1_kernel<<<blocks, WPB * 32>>>(feats, seg, wl, bl, wg, bg, n);

    finalize_kernel<<<1, C>>>();

    int total4 = n * (C / 4);
    normalize_kernel<<<(total4 + 255) / 256, 256>>>(feats, out, total4);
}

// round 2
// speedup vs baseline: 1.2001x; 1.2001x over previous
#include <cuda_runtime.h>
#include <math.h>
#include <stdint.h>

#define C 256
#define B 16
#define TILE 32              // rows per smem tile (32 KB)
#define DEPTH 3              // pipeline stages
#define THREADS 256          // 8 warps per block
#define NBLOCKS 296          // ~2 per SM

#define TILE_FLOATS (TILE * C)
#define SMEM_BYTES (DEPTH * TILE_FLOATS * 4 + DEPTH * 8 + 8)

// Scratch accumulators (device globals: no allocation allowed)
__device__ float g_S1[B * C];
__device__ float g_S2[B * C];
__device__ float g_Z[B];
__device__ float g_W[B];
__device__ float g_mean[C];
__device__ float g_rstd[C];

// ---------------------------------------------------------------------------
__global__ void zero_acc_kernel() {
    int i = blockIdx.x * blockDim.x + threadIdx.x;
    if (i < B * C) { g_S1[i] = 0.f; g_S2[i] = 0.f; }
    if (i < B)     { g_Z[i]  = 0.f; g_W[i]  = 0.f; }
}

// ---------------------------------------------------------------------------
// PTX helpers
// ---------------------------------------------------------------------------
__device__ __forceinline__ uint32_t smem_u32(const void* p) {
    uint32_t a;
    asm("{ .reg .u64 t; cvta.to.shared.u64 t, %1; cvt.u32.u64 %0, t; }"
        : "=r"(a) : "l"(p));
    return a;
}
__device__ __forceinline__ void mbar_init(uint32_t mbar, uint32_t cnt) {
    asm volatile("mbarrier.init.shared.b64 [%0], %1;" :: "r"(mbar), "r"(cnt) : "memory");
}
__device__ __forceinline__ void mbar_expect_tx(uint32_t mbar, uint32_t bytes) {
    asm volatile("mbarrier.arrive.expect_tx.shared.b64 _, [%0], %1;"
                 :: "r"(mbar), "r"(bytes) : "memory");
}
__device__ __forceinline__ void bulk_g2s(uint32_t dst, const void* src,
                                         uint32_t bytes, uint32_t mbar) {
    asm volatile(
        "cp.async.bulk.shared::cta.global.mbarrier::complete_tx::bytes [%0], [%1], %2, [%3];"
        :: "r"(dst), "l"(src), "r"(bytes), "r"(mbar) : "memory");
}
__device__ __forceinline__ void mbar_wait(uint32_t mbar, uint32_t parity) {
    uint32_t done;
    asm volatile(
        "{\n\t.reg .pred p;\n\t"
        "mbarrier.try_wait.parity.acquire.cta.shared::cta.b64 p, [%1], %2;\n\t"
        "selp.b32 %0, 1, 0, p;\n\t}"
        : "=r"(done) : "r"(mbar), "r"(parity) : "memory");
    if (!done) {
        asm volatile(
            "{\n\t.reg .pred P1;\n\t"
            "W_%=:\n\t"
            "mbarrier.try_wait.parity.acquire.cta.shared::cta.b64 P1, [%0], %1, 0x989680;\n\t"
            "@P1 bra.uni D_%=;\n\t"
            "bra.uni W_%=;\n\t"
            "D_%=:\n\t}"
            :: "r"(mbar), "r"(parity) : "memory");
    }
}

// ---------------------------------------------------------------------------
__device__ __forceinline__ void flush_acc(int segv, int lane,
                                          float* s1, float* s2,
                                          float zacc, float wacc) {
    int c0 = lane * 4;
    int c1 = 128 + lane * 4;
#pragma unroll
    for (int k = 0; k < 4; k++) {
        atomicAdd(&g_S1[segv * C + c0 + k], s1[k]);
        atomicAdd(&g_S1[segv * C + c1 + k], s1[4 + k]);
        atomicAdd(&g_S2[segv * C + c0 + k], s2[k]);
        atomicAdd(&g_S2[segv * C + c1 + k], s2[4 + k]);
    }
    if (lane == 0) {
        atomicAdd(&g_Z[segv], zacc);
        atomicAdd(&g_W[segv], wacc);
    }
}

__device__ __forceinline__ void process_row(
    float4 x0, float4 x1, int s, int lane,
    float4 wl0, float4 wl1, float4 wg0, float4 wg1,
    float blv, float bgv,
    int& cur, float* s1, float* s2, float& zacc, float& wacc)
{
    if (s != cur) {   // rare: sorted segment ids
        flush_acc(cur, lane, s1, s2, zacc, wacc);
#pragma unroll
        for (int k = 0; k < 8; k++) { s1[k] = 0.f; s2[k] = 0.f; }
        zacc = 0.f; wacc = 0.f;
        cur = s;
    }
    float dl = x0.x*wl0.x + x0.y*wl0.y + x0.z*wl0.z + x0.w*wl0.w
             + x1.x*wl1.x + x1.y*wl1.y + x1.z*wl1.z + x1.w*wl1.w;
    float dg = x0.x*wg0.x + x0.y*wg0.y + x0.z*wg0.z + x0.w*wg0.w
             + x1.x*wg1.x + x1.y*wg1.y + x1.z*wg1.z + x1.w*wg1.w;
#pragma unroll
    for (int o = 16; o; o >>= 1) {
        dl += __shfl_xor_sync(0xffffffffu, dl, o);
        dg += __shfl_xor_sync(0xffffffffu, dg, o);
    }
    float l = dl + blv;
    float g = dg + bgv;
    float e   = __expf(g);                     // g ~ N(0,1): safe unshifted
    float sgm = 1.0f / (1.0f + __expf(-l));
    float wr  = sgm * e;
    zacc += e;
    wacc += wr;
    float t;
    t = wr * x0.x; s1[0] += t; s2[0] += t * x0.x;
    t = wr * x0.y; s1[1] += t; s2[1] += t * x0.y;
    t = wr * x0.z; s1[2] += t; s2[2] += t * x0.z;
    t = wr * x0.w; s1[3] += t; s2[3] += t * x0.w;
    t = wr * x1.x; s1[4] += t; s2[4] += t * x1.x;
    t = wr * x1.y; s1[5] += t; s2[5] += t * x1.y;
    t = wr * x1.z; s1[6] += t; s2[6] += t * x1.z;
    t = wr * x1.w; s1[7] += t; s2[7] += t * x1.w;
}

// ---------------------------------------------------------------------------
// pass 1: TMA bulk-copy pipeline into smem ring, warps consume staged tiles
// ---------------------------------------------------------------------------
extern __shared__ char smem_raw[];

__global__ __launch_bounds__(THREADS, 2)
void pass1_kernel(const float* __restrict__ feats,
                  const int*   __restrict__ seg,
                  const float* __restrict__ wl,
                  const float* __restrict__ bl,
                  const float* __restrict__ wg,
                  const float* __restrict__ bg,
                  int n)
{
    float* tiles = (float*)smem_raw;
    uint64_t* mbar64 = (uint64_t*)(smem_raw + (size_t)DEPTH * TILE_FLOATS * 4);

    int ntiles = (n + TILE - 1) / TILE;
    int chunk  = (ntiles + NBLOCKS - 1) / NBLOCKS;
    int t0 = blockIdx.x * chunk;
    int t1 = min(ntiles, t0 + chunk);
    int nt = t1 - t0;
    if (nt <= 0) return;

    int tid  = threadIdx.x;
    int warp = tid >> 5;
    int lane = tid & 31;

    uint32_t mb[DEPTH];
#pragma unroll
    for (int d = 0; d < DEPTH; d++) mb[d] = smem_u32(&mbar64[d]);
    uint32_t tile_s[DEPTH];
#pragma unroll
    for (int d = 0; d < DEPTH; d++) tile_s[d] = smem_u32(tiles + d * TILE_FLOATS);

    if (tid == 0) {
#pragma unroll
        for (int d = 0; d < DEPTH; d++) mbar_init(mb[d], 1);
    }
    __syncthreads();

    // prologue: fill pipeline
    if (tid == 0) {
        int pre = min(DEPTH, nt);
        for (int i = 0; i < pre; i++) {
            int t = t0 + i;
            int rows = min(TILE, n - t * TILE);
            uint32_t bytes = (uint32_t)rows * C * 4;
            mbar_expect_tx(mb[i], bytes);
            bulk_g2s(tile_s[i], feats + (size_t)t * TILE_FLOATS, bytes, mb[i]);
        }
    }

    // per-warp weight registers + accumulators
    const float4* wl4 = (const float4*)wl;
    const float4* wg4 = (const float4*)wg;
    float4 wl0 = wl4[lane], wl1 = wl4[32 + lane];
    float4 wg0 = wg4[lane], wg1 = wg4[32 + lane];
    float  blv = bl[0],     bgv = bg[0];

    float s1[8], s2[8];
#pragma unroll
    for (int k = 0; k < 8; k++) { s1[k] = 0.f; s2[k] = 0.f; }
    float zacc = 0.f, wacc = 0.f;
    int cur = seg[min(n - 1, t0 * TILE + warp * 4)];

    for (int i = 0; i < nt; i++) {
        int st = i % DEPTH;
        uint32_t parity = (uint32_t)((i / DEPTH) & 1);
        mbar_wait(mb[st], parity);

        const float* tp = tiles + st * TILE_FLOATS;
        int base = (t0 + i) * TILE;
        int rows = min(TILE, n - base);
#pragma unroll
        for (int j = 0; j < 4; j++) {
            int lr = warp * 4 + j;              // warp-uniform
            if (lr < rows) {
                int gr = base + lr;
                int sv = seg[gr];
                float4 x0 = *(const float4*)(tp + lr * C + lane * 4);
                float4 x1 = *(const float4*)(tp + lr * C + 128 + lane * 4);
                process_row(x0, x1, sv, lane, wl0, wl1, wg0, wg1, blv, bgv,
                            cur, s1, s2, zacc, wacc);
            }
        }
        __syncthreads();   // all warps done with stage st
        if (tid == 0 && i + DEPTH < nt) {
            int t = t0 + i + DEPTH;
            int rows2 = min(TILE, n - t * TILE);
            uint32_t bytes = (uint32_t)rows2 * C * 4;
            mbar_expect_tx(mb[st], bytes);
            bulk_g2s(tile_s[st], feats + (size_t)t * TILE_FLOATS, bytes, mb[st]);
        }
    }
    flush_acc(cur, lane, s1, s2, zacc, wacc);
}

// ---------------------------------------------------------------------------
__global__ void finalize_kernel() {
    __shared__ float invZ[B];
    __shared__ float invU;
    int t = threadIdx.x;
    if (t < B) invZ[t] = 1.0f / g_Z[t];
    __syncthreads();
    if (t == 0) {
        float U = 0.f;
        for (int b = 0; b < B; b++) U += g_W[b] * invZ[b];
        invU = 1.0f / U;
    }
    __syncthreads();
    float m1 = 0.f, m2 = 0.f;
    for (int b = 0; b < B; b++) {
        m1 += g_S1[b * C + t] * invZ[b];
        m2 += g_S2[b * C + t] * invZ[b];
    }
    float iu = invU;
    m1 *= iu;
    m2 *= iu;
    float var = m2 - m1 * m1;   // sum(weight) == 1 exactly in the math
    g_mean[t] = m1;
    g_rstd[t] = 1.0f / sqrtf(var);
}

// ---------------------------------------------------------------------------
// pass 2: out = (x - mean[c]) * rstd[c]
// Each block owns 1024 consecutive float4; thread handles 4 strided by 256.
// (base + 256k) & 63 is invariant -> one mean/rstd load, 4 independent LDG.128.
// ---------------------------------------------------------------------------
__global__ __launch_bounds__(256)
void normalize_kernel(const float* __restrict__ feats,
                      float* __restrict__ out, int total4)
{
    int base = blockIdx.x * 1024 + threadIdx.x;
    if (base >= total4) return;
    const float4* f4 = (const float4*)feats;
    float4*       o4 = (float4*)out;
    const float4* m4 = (const float4*)g_mean;
    const float4* r4 = (const float4*)g_rstd;

    int cf = base & 63;
    float4 m  = m4[cf];
    float4 rs = r4[cf];

#pragma unroll
    for (int k = 0; k < 4; k++) {
        int i = base + k * 256;
        if (i < total4) {
            float4 x = __ldcs(f4 + i);
            float4 y;
            y.x = (x.x - m.x) * rs.x;
            y.y = (x.y - m.y) * rs.y;
            y.z = (x.z - m.z) * rs.z;
            y.w = (x.w - m.w) * rs.w;
            __stcs(o4 + i, y);
        }
    }
}

// ---------------------------------------------------------------------------
extern "C" void kernel_launch(void* const* d_in, const int* in_sizes, int n_in,
                              void* d_out, int out_size) {
    const float* feats = (const float*)d_in[0];
    const int*   seg   = (const int*)  d_in[1];
    const float* wl    = (const float*)d_in[2];
    const float* bl    = (const float*)d_in[3];
    const float* wg    = (const float*)d_in[4];
    const float* bg    = (const float*)d_in[5];
    float*       out   = (float*)d_out;

    int n = in_sizes[0] / C;

    cudaFuncSetAttribute(pass1_kernel,
                         cudaFuncAttributeMaxDynamicSharedMemorySize, SMEM_BYTES);

    zero_acc_kernel<<<(B * C + 255) / 256, 256>>>();

    pass1_kernel<<<NBLOCKS, THREADS, SMEM_BYTES>>>(feats, seg, wl, bl, wg, bg, n);

    finalize_kernel<<<1, C>>>();

    int total4 = n * (C / 4);
    normalize_kernel<<<(total4 + 1023) / 1024, 256>>>(feats, out, total4);
}

// round 3
// speedup vs baseline: 1.2442x; 1.0367x over previous
#include <cuda_runtime.h>
#include <math.h>
#include <stdint.h>

#define C 256
#define B 16
#define TILE 32              // rows per smem tile (32 KB)
#define DEPTH 3              // pipeline stages
#define THREADS 256          // 8 warps per block
#define NBLOCKS 296          // 2 per SM

#define TILE_FLOATS (TILE * C)
#define SMEM_BYTES (DEPTH * TILE_FLOATS * 4 + DEPTH * 8 + 8)

// Scratch accumulators (device globals; zeroed at end of finalize each replay)
__device__ float g_S1[B * C];
__device__ float g_S2[B * C];
__device__ float g_Z[B];
__device__ float g_W[B];
__device__ float g_mean[C];
__device__ float g_rstd[C];

// ---------------------------------------------------------------------------
// PTX helpers
// ---------------------------------------------------------------------------
__device__ __forceinline__ uint32_t smem_u32(const void* p) {
    uint32_t a;
    asm("{ .reg .u64 t; cvta.to.shared.u64 t, %1; cvt.u32.u64 %0, t; }"
        : "=r"(a) : "l"(p));
    return a;
}
__device__ __forceinline__ void mbar_init(uint32_t mbar, uint32_t cnt) {
    asm volatile("mbarrier.init.shared.b64 [%0], %1;" :: "r"(mbar), "r"(cnt) : "memory");
}
__device__ __forceinline__ void mbar_expect_tx(uint32_t mbar, uint32_t bytes) {
    asm volatile("mbarrier.arrive.expect_tx.shared.b64 _, [%0], %1;"
                 :: "r"(mbar), "r"(bytes) : "memory");
}
__device__ __forceinline__ void bulk_g2s(uint32_t dst, const void* src,
                                         uint32_t bytes, uint32_t mbar) {
    asm volatile(
        "cp.async.bulk.shared::cta.global.mbarrier::complete_tx::bytes [%0], [%1], %2, [%3];"
        :: "r"(dst), "l"(src), "r"(bytes), "r"(mbar) : "memory");
}
__device__ __forceinline__ void mbar_wait(uint32_t mbar, uint32_t parity) {
    uint32_t done;
    asm volatile(
        "{\n\t.reg .pred p;\n\t"
        "mbarrier.try_wait.parity.acquire.cta.shared::cta.b64 p, [%1], %2;\n\t"
        "selp.b32 %0, 1, 0, p;\n\t}"
        : "=r"(done) : "r"(mbar), "r"(parity) : "memory");
    if (!done) {
        asm volatile(
            "{\n\t.reg .pred P1;\n\t"
            "W_%=:\n\t"
            "mbarrier.try_wait.parity.acquire.cta.shared::cta.b64 P1, [%0], %1, 0x989680;\n\t"
            "@P1 bra.uni D_%=;\n\t"
            "bra.uni W_%=;\n\t"
            "D_%=:\n\t}"
            :: "r"(mbar), "r"(parity) : "memory");
    }
}

// ---------------------------------------------------------------------------
__device__ __forceinline__ void flush_acc(int segv, int lane,
                                          float* s1, float* s2,
                                          float zacc, float wacc) {
    int c0 = lane * 4;
    int c1 = 128 + lane * 4;
#pragma unroll
    for (int k = 0; k < 4; k++) {
        atomicAdd(&g_S1[segv * C + c0 + k], s1[k]);
        atomicAdd(&g_S1[segv * C + c1 + k], s1[4 + k]);
        atomicAdd(&g_S2[segv * C + c0 + k], s2[k]);
        atomicAdd(&g_S2[segv * C + c1 + k], s2[4 + k]);
    }
    if (lane == 0) {
        atomicAdd(&g_Z[segv], zacc);
        atomicAdd(&g_W[segv], wacc);
    }
}

#define DOT8(x0, x1, w0, w1) \
    (x0.x*w0.x + x0.y*w0.y + x0.z*w0.z + x0.w*w0.w + \
     x1.x*w1.x + x1.y*w1.y + x1.z*w1.z + x1.w*w1.w)

__device__ __forceinline__ void accum_row(float wr, float4 x0, float4 x1,
                                          float* s1, float* s2) {
    float t;
    t = wr * x0.x; s1[0] += t; s2[0] += t * x0.x;
    t = wr * x0.y; s1[1] += t; s2[1] += t * x0.y;
    t = wr * x0.z; s1[2] += t; s2[2] += t * x0.z;
    t = wr * x0.w; s1[3] += t; s2[3] += t * x0.w;
    t = wr * x1.x; s1[4] += t; s2[4] += t * x1.x;
    t = wr * x1.y; s1[5] += t; s2[5] += t * x1.y;
    t = wr * x1.z; s1[6] += t; s2[6] += t * x1.z;
    t = wr * x1.w; s1[7] += t; s2[7] += t * x1.w;
}

__device__ __forceinline__ void process_row_slow(
    float4 x0, float4 x1, int s, int lane,
    float4 wl0, float4 wl1, float4 wg0, float4 wg1,
    float blv, float bgv,
    int& cur, float* s1, float* s2, float& zacc, float& wacc)
{
    if (s != cur) {
        flush_acc(cur, lane, s1, s2, zacc, wacc);
#pragma unroll
        for (int k = 0; k < 8; k++) { s1[k] = 0.f; s2[k] = 0.f; }
        zacc = 0.f; wacc = 0.f;
        cur = s;
    }
    float dl = DOT8(x0, x1, wl0, wl1);
    float dg = DOT8(x0, x1, wg0, wg1);
#pragma unroll
    for (int o = 16; o; o >>= 1) {
        dl += __shfl_xor_sync(0xffffffffu, dl, o);
        dg += __shfl_xor_sync(0xffffffffu, dg, o);
    }
    float e   = __expf(dg + bgv);
    float sgm = 1.0f / (1.0f + __expf(-(dl + blv)));
    float wr  = sgm * e;
    zacc += e;
    wacc += wr;
    accum_row(wr, x0, x1, s1, s2);
}

// ---------------------------------------------------------------------------
// pass 1: TMA bulk-copy pipeline into smem ring, warps consume staged tiles
// ---------------------------------------------------------------------------
extern __shared__ char smem_raw[];

__global__ __launch_bounds__(THREADS, 2)
void pass1_kernel(const float* __restrict__ feats,
                  const int*   __restrict__ seg,
                  const float* __restrict__ wl,
                  const float* __restrict__ bl,
                  const float* __restrict__ wg,
                  const float* __restrict__ bg,
                  int n)
{
    float* tiles = (float*)smem_raw;
    uint64_t* mbar64 = (uint64_t*)(smem_raw + (size_t)DEPTH * TILE_FLOATS * 4);

    int ntiles = (n + TILE - 1) / TILE;
    int chunk  = (ntiles + NBLOCKS - 1) / NBLOCKS;
    int t0 = blockIdx.x * chunk;
    int t1 = min(ntiles, t0 + chunk);
    int nt = t1 - t0;
    if (nt <= 0) return;

    int tid  = threadIdx.x;
    int warp = tid >> 5;
    int lane = tid & 31;

    uint32_t mb[DEPTH];
#pragma unroll
    for (int d = 0; d < DEPTH; d++) mb[d] = smem_u32(&mbar64[d]);
    uint32_t tile_s[DEPTH];
#pragma unroll
    for (int d = 0; d < DEPTH; d++) tile_s[d] = smem_u32(tiles + d * TILE_FLOATS);

    if (tid == 0) {
#pragma unroll
        for (int d = 0; d < DEPTH; d++) mbar_init(mb[d], 1);
    }
    __syncthreads();

    if (tid == 0) {
        int pre = min(DEPTH, nt);
        for (int i = 0; i < pre; i++) {
            int t = t0 + i;
            int rows = min(TILE, n - t * TILE);
            uint32_t bytes = (uint32_t)rows * C * 4;
            mbar_expect_tx(mb[i], bytes);
            bulk_g2s(tile_s[i], feats + (size_t)t * TILE_FLOATS, bytes, mb[i]);
        }
    }

    const float4* wl4 = (const float4*)wl;
    const float4* wg4 = (const float4*)wg;
    float4 wl0 = wl4[lane], wl1 = wl4[32 + lane];
    float4 wg0 = wg4[lane], wg1 = wg4[32 + lane];
    float  blv = bl[0],     bgv = bg[0];

    float s1[8], s2[8];
#pragma unroll
    for (int k = 0; k < 8; k++) { s1[k] = 0.f; s2[k] = 0.f; }
    float zacc = 0.f, wacc = 0.f;
    int cur = __ldg(&seg[min(n - 1, t0 * TILE + warp * 4)]);

    for (int i = 0; i < nt; i++) {
        int st = i % DEPTH;
        uint32_t parity = (uint32_t)((i / DEPTH) & 1);
        mbar_wait(mb[st], parity);

        const float* tp = tiles + st * TILE_FLOATS;
        int base = (t0 + i) * TILE;
        int rows = min(TILE, n - base);

        int s_lo = __ldg(&seg[base]);
        int s_hi = __ldg(&seg[base + rows - 1]);

        if (s_lo == s_hi && rows == TILE) {
            // ------- fast path: whole tile in one segment, full 4 rows -------
            if (s_lo != cur) {
                flush_acc(cur, lane, s1, s2, zacc, wacc);
#pragma unroll
                for (int k = 0; k < 8; k++) { s1[k] = 0.f; s2[k] = 0.f; }
                zacc = 0.f; wacc = 0.f;
                cur = s_lo;
            }
            const float* rp = tp + (warp * 4) * C + lane * 4;
            float4 xa0 = *(const float4*)(rp);
            float4 xa1 = *(const float4*)(rp + 128);
            float4 xb0 = *(const float4*)(rp + C);
            float4 xb1 = *(const float4*)(rp + C + 128);
            float4 xc0 = *(const float4*)(rp + 2 * C);
            float4 xc1 = *(const float4*)(rp + 2 * C + 128);
            float4 xd0 = *(const float4*)(rp + 3 * C);
            float4 xd1 = *(const float4*)(rp + 3 * C + 128);

            float dla = DOT8(xa0, xa1, wl0, wl1), dga = DOT8(xa0, xa1, wg0, wg1);
            float dlb = DOT8(xb0, xb1, wl0, wl1), dgb = DOT8(xb0, xb1, wg0, wg1);
            float dlc = DOT8(xc0, xc1, wl0, wl1), dgc = DOT8(xc0, xc1, wg0, wg1);
            float dld = DOT8(xd0, xd1, wl0, wl1), dgd = DOT8(xd0, xd1, wg0, wg1);

            // 8 interleaved butterfly chains
#pragma unroll
            for (int o = 16; o; o >>= 1) {
                dla += __shfl_xor_sync(0xffffffffu, dla, o);
                dga += __shfl_xor_sync(0xffffffffu, dga, o);
                dlb += __shfl_xor_sync(0xffffffffu, dlb, o);
                dgb += __shfl_xor_sync(0xffffffffu, dgb, o);
                dlc += __shfl_xor_sync(0xffffffffu, dlc, o);
                dgc += __shfl_xor_sync(0xffffffffu, dgc, o);
                dld += __shfl_xor_sync(0xffffffffu, dld, o);
                dgd += __shfl_xor_sync(0xffffffffu, dgd, o);
            }
            float ea = __expf(dga + bgv);
            float eb = __expf(dgb + bgv);
            float ec = __expf(dgc + bgv);
            float ed = __expf(dgd + bgv);
            float wra = ea / (1.0f + __expf(-(dla + blv)));
            float wrb = eb / (1.0f + __expf(-(dlb + blv)));
            float wrc = ec / (1.0f + __expf(-(dlc + blv)));
            float wrd = ed / (1.0f + __expf(-(dld + blv)));
            zacc += (ea + eb) + (ec + ed);
            wacc += (wra + wrb) + (wrc + wrd);
            accum_row(wra, xa0, xa1, s1, s2);
            accum_row(wrb, xb0, xb1, s1, s2);
            accum_row(wrc, xc0, xc1, s1, s2);
            accum_row(wrd, xd0, xd1, s1, s2);
        } else {
            // ------- slow path: tile crosses a segment boundary (<=15 tiles) -------
#pragma unroll
            for (int j = 0; j < 4; j++) {
                int lr = warp * 4 + j;
                if (lr < rows) {
                    int sv = __ldg(&seg[base + lr]);
                    float4 x0 = *(const float4*)(tp + lr * C + lane * 4);
                    float4 x1 = *(const float4*)(tp + lr * C + 128 + lane * 4);
                    process_row_slow(x0, x1, sv, lane, wl0, wl1, wg0, wg1,
                                     blv, bgv, cur, s1, s2, zacc, wacc);
                }
            }
        }

        __syncthreads();   // all warps done with stage st
        if (tid == 0 && i + DEPTH < nt) {
            int t = t0 + i + DEPTH;
            int rows2 = min(TILE, n - t * TILE);
            uint32_t bytes = (uint32_t)rows2 * C * 4;
            mbar_expect_tx(mb[st], bytes);
            bulk_g2s(tile_s[st], feats + (size_t)t * TILE_FLOATS, bytes, mb[st]);
        }
    }
    flush_acc(cur, lane, s1, s2, zacc, wacc);
}

// ---------------------------------------------------------------------------
// finalize: fold 16 segments into mean/rstd, then RE-ZERO accumulators so the
// next graph replay starts clean (replaces the standalone zero kernel).
// ---------------------------------------------------------------------------
__global__ void finalize_kernel() {
    __shared__ float invZ[B];
    __shared__ float invU;
    int t = threadIdx.x;
    if (t < B) invZ[t] = 1.0f / g_Z[t];
    __syncthreads();
    if (t == 0) {
        float U = 0.f;
        for (int b = 0; b < B; b++) U += g_W[b] * invZ[b];
        invU = 1.0f / U;
    }
    __syncthreads();
    float m1 = 0.f, m2 = 0.f;
    for (int b = 0; b < B; b++) {
        m1 += g_S1[b * C + t] * invZ[b];
        m2 += g_S2[b * C + t] * invZ[b];
    }
    float iu = invU;
    m1 *= iu;
    m2 *= iu;
    float var = m2 - m1 * m1;   // sum(weight) == 1 exactly in the math
    g_mean[t] = m1;
    g_rstd[t] = 1.0f / sqrtf(var);
    // re-zero for next replay
    for (int b = 0; b < B; b++) {
        g_S1[b * C + t] = 0.f;
        g_S2[b * C + t] = 0.f;
    }
    if (t < B) { g_Z[t] = 0.f; g_W[t] = 0.f; }
}

// ---------------------------------------------------------------------------
// pass 2: out = (x - mean[c]) * rstd[c]
// ---------------------------------------------------------------------------
__global__ __launch_bounds__(256)
void normalize_kernel(const float* __restrict__ feats,
                      float* __restrict__ out, int total4)
{
    int base = blockIdx.x * 1024 + threadIdx.x;
    if (base >= total4) return;
    const float4* f4 = (const float4*)feats;
    float4*       o4 = (float4*)out;
    const float4* m4 = (const float4*)g_mean;
    const float4* r4 = (const float4*)g_rstd;

    int cf = base & 63;
    float4 m  = m4[cf];
    float4 rs = r4[cf];

#pragma unroll
    for (int k = 0; k < 4; k++) {
        int i = base + k * 256;
        if (i < total4) {
            float4 x = __ldcs(f4 + i);
            float4 y;
            y.x = (x.x - m.x) * rs.x;
            y.y = (x.y - m.y) * rs.y;
            y.z = (x.z - m.z) * rs.z;
            y.w = (x.w - m.w) * rs.w;
            __stcs(o4 + i, y);
        }
    }
}

// ---------------------------------------------------------------------------
extern "C" void kernel_launch(void* const* d_in, const int* in_sizes, int n_in,
                              void* d_out, int out_size) {
    const float* feats = (const float*)d_in[0];
    const int*   seg   = (const int*)  d_in[1];
    const float* wl    = (const float*)d_in[2];
    const float* bl    = (const float*)d_in[3];
    const float* wg    = (const float*)d_in[4];
    const float* bg    = (const float*)d_in[5];
    float*       out   = (float*)d_out;

    int n = in_sizes[0] / C;

    cudaFuncSetAttribute(pass1_kernel,
                         cudaFuncAttributeMaxDynamicSharedMemorySize, SMEM_BYTES);

    pass1_kernel<<<NBLOCKS, THREADS, SMEM_BYTES>>>(feats, seg, wl, bl, wg, bg, n);

    finalize_kernel<<<1, C>>>();

    int total4 = n * (C / 4);
    normalize_kernel<<<(total4 + 1023) / 1024, 256>>>(feats, out, total4);
}